// round 3
// baseline (speedup 1.0000x reference)
#include <cuda_runtime.h>
#include <cuda_bf16.h>

#define OUT_DIM 64
#define IN_DIM 128
#define MAX_POOL 16384
#define MAX_POOL_SM 10240      // fused-prep smem histogram capacity
#define MAX_EDGES 65536
#define CHUNK 8
#define XROW 144               // skewed x row: 4 quadrants * 36 words

__device__ int g_counts[MAX_POOL];
__device__ int g_offsets[MAX_POOL];
__device__ int g_cursor[MAX_POOL];
__device__ int g_sorted[MAX_EDGES];

// ---------------------------------------------------------------------------
// Fused prep: histogram + exclusive scan + scatter in ONE single-block kernel.
// npool ints live in SMEM (<= MAX_POOL_SM). Replaces a 4-kernel chain.
__global__ __launch_bounds__(1024) void prep_kernel(const int* __restrict__ idx,
                                                    int E, int npool) {
    __shared__ int sc[MAX_POOL_SM];
    __shared__ int ws[32];
    int tid = threadIdx.x;

    for (int i = tid; i < npool; i += 1024) sc[i] = 0;
    __syncthreads();

    for (int i = tid; i < E; i += 1024) atomicAdd(&sc[idx[i]], 1);
    __syncthreads();

    // hierarchical exclusive scan: serial-per-thread + warp shfl scan
    int per = (npool + 1023) >> 10;          // <= 16 given MAX_POOL_SM
    int lo = min(tid * per, npool);
    int hi = min(lo + per, npool);
    int local[16];
    int sum = 0;
    for (int i = lo; i < hi; i++) { local[i - lo] = sum; sum += sc[i]; }

    int lane = tid & 31, wid = tid >> 5;
    int v = sum;
    #pragma unroll
    for (int o = 1; o < 32; o <<= 1) {
        int t = __shfl_up_sync(0xffffffffu, v, o);
        if (lane >= o) v += t;
    }
    if (lane == 31) ws[wid] = v;
    __syncthreads();
    if (wid == 0) {
        int t = ws[lane];
        #pragma unroll
        for (int o = 1; o < 32; o <<= 1) {
            int u = __shfl_up_sync(0xffffffffu, t, o);
            if (lane >= o) t += u;
        }
        ws[lane] = t;
    }
    __syncthreads();
    int base = (v - sum) + (wid > 0 ? ws[wid - 1] : 0);

    for (int i = lo; i < hi; i++) {
        int c = sc[i];
        int off = base + local[i - lo];
        g_counts[i]  = c;
        g_offsets[i] = off;
        sc[i] = off;                          // becomes the scatter cursor
    }
    __syncthreads();

    for (int i = tid; i < E; i += 1024) {
        int p = atomicAdd(&sc[idx[i]], 1);
        g_sorted[p] = i;
    }
}

// ---------------------------------------------------------------------------
// Fallback prep chain (npool/E beyond the fused kernel's SMEM capacity)
__global__ void zero_counts_kernel(int npool) {
    int i = blockIdx.x * blockDim.x + threadIdx.x;
    if (i < npool) g_counts[i] = 0;
}
__global__ void hist_kernel(const int* __restrict__ idx, int n) {
    int i = blockIdx.x * blockDim.x + threadIdx.x;
    if (i < n) atomicAdd(&g_counts[idx[i]], 1);
}
__global__ void scan_kernel(int npool) {
    int tid = threadIdx.x;
    int per = (npool + 1023) >> 10;
    int lo = min(tid * per, npool);
    int hi = min(lo + per, npool);
    int local[16];
    int sum = 0;
    for (int i = lo; i < hi; i++) { local[i - lo] = sum; sum += g_counts[i]; }
    int lane = tid & 31, wid = tid >> 5;
    int v = sum;
    #pragma unroll
    for (int o = 1; o < 32; o <<= 1) {
        int t = __shfl_up_sync(0xffffffffu, v, o);
        if (lane >= o) v += t;
    }
    __shared__ int ws[32];
    if (lane == 31) ws[wid] = v;
    __syncthreads();
    if (wid == 0) {
        int t = ws[lane];
        #pragma unroll
        for (int o = 1; o < 32; o <<= 1) {
            int u = __shfl_up_sync(0xffffffffu, t, o);
            if (lane >= o) t += u;
        }
        ws[lane] = t;
    }
    __syncthreads();
    int base = (v - sum) + (wid > 0 ? ws[wid - 1] : 0);
    for (int i = lo; i < hi; i++) {
        int off = base + local[i - lo];
        g_offsets[i] = off;
        g_cursor[i]  = off;
    }
}
__global__ void scatter_kernel(const int* __restrict__ idx, int n) {
    int i = blockIdx.x * blockDim.x + threadIdx.x;
    if (i < n) {
        int p = atomicAdd(&g_cursor[idx[i]], 1);
        g_sorted[p] = i;
    }
}

// ---------------------------------------------------------------------------
// Compute: one CTA per pool entry.
// Key identity: thread tid=(r*4+q) needs W[r][q*32..q*32+31] = W linear words
// [tid*32, tid*32+32). So we do a fully-coalesced scalar identity copy
// GMEM->SMEM into a padded buffer (phys = a + a/32), then each thread loads
// its 32 words at sWp[tid*33 + c] — banks (tid+c)%32 all distinct, zero
// conflicts, nL=1 per LDG. This removes the 32-lines-per-instruction L1tex
// wavefront storm of the direct strided register load.
__global__ __launch_bounds__(256) void compute_kernel(
    const float* __restrict__ x,      // [E, 128]
    const float* __restrict__ Wpool,  // [P, 64, 128]
    const float* __restrict__ bpool,  // [P, 64]
    float* __restrict__ out)          // [E, 64]
{
    int w = blockIdx.x;
    int tid = threadIdx.x;

    __shared__ float sWp[8448];          // 8192 + 256 pad words
    __shared__ float sx[CHUNK][XROW];
    __shared__ int   se[CHUNK];

    int cnt   = g_counts[w];             // issued early, latency hidden by copy
    int start = g_offsets[w];

    // Coalesced, conflict-free identity copy of W into padded SMEM.
    const float* Wg = Wpool + (size_t)w * (OUT_DIM * IN_DIM);
    #pragma unroll
    for (int i = 0; i < 32; i++) {
        int a = tid + 256 * i;
        sWp[a + (a >> 5)] = Wg[a];
    }

    if (cnt == 0) return;                // uniform branch (cnt same for all)
    __syncthreads();

    int r = tid >> 2;                    // output row 0..63
    int q = tid & 3;                     // K quadrant

    // Conflict-free register load: word a = tid*32+c -> phys tid*33+c.
    float wreg[32];
    #pragma unroll
    for (int c = 0; c < 32; c++)
        wreg[c] = sWp[tid * 33 + c];

    float bias = bpool[(size_t)w * OUT_DIM + r];

    for (int base = 0; base < cnt; base += CHUNK) {
        int nch = min(CHUNK, cnt - base);
        __syncthreads();                              // protect previous chunk
        if (tid < nch) se[tid] = g_sorted[start + base + tid];
        __syncthreads();

        // Coalesced x prefetch into skewed SMEM: warp c loads edge slot c.
        {
            int c = tid >> 5;
            int p = tid & 31;
            if (c < nch) {
                float4 v = reinterpret_cast<const float4*>(x)[(size_t)se[c] * 32 + p];
                int word = (p >> 3) * 36 + ((p & 7) << 2);
                *reinterpret_cast<float4*>(&sx[c][word]) = v;
            }
        }
        __syncthreads();

        for (int c = 0; c < nch; c++) {
            const float* xs = &sx[c][q * 36];
            float a0 = 0.f, a1 = 0.f, a2 = 0.f, a3 = 0.f;
            #pragma unroll
            for (int i = 0; i < 8; i++) {
                float4 xv = *reinterpret_cast<const float4*>(&xs[4 * i]);
                a0 = fmaf(wreg[4 * i + 0], xv.x, a0);
                a1 = fmaf(wreg[4 * i + 1], xv.y, a1);
                a2 = fmaf(wreg[4 * i + 2], xv.z, a2);
                a3 = fmaf(wreg[4 * i + 3], xv.w, a3);
            }
            float acc = (a0 + a1) + (a2 + a3);
            acc += __shfl_xor_sync(0xffffffffu, acc, 1);
            acc += __shfl_xor_sync(0xffffffffu, acc, 2);
            if (q == 0) {
                float y = acc + bias;
                out[(size_t)se[c] * OUT_DIM + r] = y > 0.f ? y : 0.f;
            }
        }
    }
}

// ---------------------------------------------------------------------------
extern "C" void kernel_launch(void* const* d_in, const int* in_sizes, int n_in,
                              void* d_out, int out_size) {
    const float* x     = (const float*)d_in[0];  // [E,128,1]
    const int*   idx   = (const int*)d_in[1];    // [E]
    const float* Wpool = (const float*)d_in[2];  // [P,64,128]
    const float* bpool = (const float*)d_in[3];  // [P,64,1]
    float* out = (float*)d_out;                  // [E,64,1]

    int E     = in_sizes[1];
    int npool = in_sizes[3] / OUT_DIM;

    if (npool <= MAX_POOL_SM && E <= MAX_EDGES) {
        prep_kernel<<<1, 1024>>>(idx, E, npool);
    } else {
        int eb = (E + 255) / 256;
        int pb = (npool + 255) / 256;
        zero_counts_kernel<<<pb, 256>>>(npool);
        hist_kernel<<<eb, 256>>>(idx, E);
        scan_kernel<<<1, 1024>>>(npool);
        scatter_kernel<<<eb, 256>>>(idx, E);
    }
    compute_kernel<<<npool, 256>>>(x, Wpool, bpool, out);
}

// round 4
// speedup vs baseline: 1.3344x; 1.3344x over previous
#include <cuda_runtime.h>
#include <cuda_bf16.h>

#define OUT_DIM 64
#define IN_DIM 128
#define MAX_POOL 16384
#define MAX_EDGES 65536

__device__ int g_counts[MAX_POOL];
__device__ int g_offsets[MAX_POOL];
__device__ int g_cursor[MAX_POOL];
__device__ int g_sorted[MAX_EDGES];

// ---------------------------------------------------------------------------
__global__ void hist_kernel(const int* __restrict__ idx, int n) {
    int i = blockIdx.x * blockDim.x + threadIdx.x;
    if (i < n) atomicAdd(&g_counts[idx[i]], 1);
}

// single-block hierarchical exclusive scan (npool <= 16384)
__global__ __launch_bounds__(1024) void scan_kernel(int npool) {
    int tid = threadIdx.x;
    int per = (npool + 1023) >> 10;
    int lo = min(tid * per, npool);
    int hi = min(lo + per, npool);
    int local[16];
    int sum = 0;
    for (int i = lo; i < hi; i++) { local[i - lo] = sum; sum += g_counts[i]; }
    int lane = tid & 31, wid = tid >> 5;
    int v = sum;
    #pragma unroll
    for (int o = 1; o < 32; o <<= 1) {
        int t = __shfl_up_sync(0xffffffffu, v, o);
        if (lane >= o) v += t;
    }
    __shared__ int ws[32];
    if (lane == 31) ws[wid] = v;
    __syncthreads();
    if (wid == 0) {
        int t = ws[lane];
        #pragma unroll
        for (int o = 1; o < 32; o <<= 1) {
            int u = __shfl_up_sync(0xffffffffu, t, o);
            if (lane >= o) t += u;
        }
        ws[lane] = t;
    }
    __syncthreads();
    int base = (v - sum) + (wid > 0 ? ws[wid - 1] : 0);
    for (int i = lo; i < hi; i++) {
        int off = base + local[i - lo];
        g_offsets[i] = off;
        g_cursor[i]  = off;
    }
}

__global__ void scatter_kernel(const int* __restrict__ idx, int n) {
    int i = blockIdx.x * blockDim.x + threadIdx.x;
    if (i < n) {
        int p = atomicAdd(&g_cursor[idx[i]], 1);
        g_sorted[p] = i;
    }
}

// ---------------------------------------------------------------------------
// Warp-autonomous compute: zero SMEM, zero barriers.
// Warp w of the CTA owns output rows [8w, 8w+8). Lane l holds, in registers,
// W[8w+j][4l..4l+4) for j=0..7 (loaded via 8 perfectly-coalesced 512B LDG.128
// warp transactions) and x[4l..4l+4) per edge (one coalesced LDG.128).
// A 5-step shfl fold reduces the 8 row-partials across 32 lanes.
__global__ __launch_bounds__(256) void compute_kernel(
    const float* __restrict__ x,      // [E, 128]
    const float* __restrict__ Wpool,  // [P, 64, 128]
    const float* __restrict__ bpool,  // [P, 64]
    float* __restrict__ out)          // [E, 64]
{
    int w    = blockIdx.x;
    int warp = threadIdx.x >> 5;
    int lane = threadIdx.x & 31;

    int cnt = g_counts[w];
    if (cnt == 0) return;
    int start = g_offsets[w];

    // W slice: 8 x LDG.128, each warp instruction = 512B contiguous.
    const float4* Wg = reinterpret_cast<const float4*>(Wpool) + (size_t)w * 2048 + warp * 256;
    float4 wv[8];
    #pragma unroll
    for (int i = 0; i < 8; i++)
        wv[i] = Wg[i * 32 + lane];   // wv[i] = W[8*warp+i][4l..4l+4)

    // Row this lane will finally own: bit-reversed low-3 lane bits.
    int rloc = 4 * (lane & 1) + 2 * ((lane >> 1) & 1) + ((lane >> 2) & 1);
    float bias = bpool[(size_t)w * OUT_DIM + 8 * warp + rloc];

    const float4* X = reinterpret_cast<const float4*>(x);

    // Software-pipelined edge loop.
    int e = g_sorted[start];
    float4 xv = X[(size_t)e * 32 + lane];

    for (int t = 0; t < cnt; t++) {
        int e_next = 0;
        float4 xv_next = make_float4(0.f, 0.f, 0.f, 0.f);
        if (t + 1 < cnt) {
            e_next  = g_sorted[start + t + 1];
            xv_next = X[(size_t)e_next * 32 + lane];
        }

        // 8 row partials over this lane's 4 k's.
        float v0 = wv[0].x * xv.x, v1 = wv[1].x * xv.x, v2 = wv[2].x * xv.x, v3 = wv[3].x * xv.x;
        float v4 = wv[4].x * xv.x, v5 = wv[5].x * xv.x, v6 = wv[6].x * xv.x, v7 = wv[7].x * xv.x;
        v0 = fmaf(wv[0].y, xv.y, v0); v1 = fmaf(wv[1].y, xv.y, v1);
        v2 = fmaf(wv[2].y, xv.y, v2); v3 = fmaf(wv[3].y, xv.y, v3);
        v4 = fmaf(wv[4].y, xv.y, v4); v5 = fmaf(wv[5].y, xv.y, v5);
        v6 = fmaf(wv[6].y, xv.y, v6); v7 = fmaf(wv[7].y, xv.y, v7);
        v0 = fmaf(wv[0].z, xv.z, v0); v1 = fmaf(wv[1].z, xv.z, v1);
        v2 = fmaf(wv[2].z, xv.z, v2); v3 = fmaf(wv[3].z, xv.z, v3);
        v4 = fmaf(wv[4].z, xv.z, v4); v5 = fmaf(wv[5].z, xv.z, v5);
        v6 = fmaf(wv[6].z, xv.z, v6); v7 = fmaf(wv[7].z, xv.z, v7);
        v0 = fmaf(wv[0].w, xv.w, v0); v1 = fmaf(wv[1].w, xv.w, v1);
        v2 = fmaf(wv[2].w, xv.w, v2); v3 = fmaf(wv[3].w, xv.w, v3);
        v4 = fmaf(wv[4].w, xv.w, v4); v5 = fmaf(wv[5].w, xv.w, v5);
        v6 = fmaf(wv[6].w, xv.w, v6); v7 = fmaf(wv[7].w, xv.w, v7);

        // Step 1 (xor 1): fold 8 rows -> 4. Even lanes keep rows 0-3, odd 4-7.
        bool b0 = lane & 1;
        float p0 = __shfl_xor_sync(~0u, v0, 1), p1 = __shfl_xor_sync(~0u, v1, 1);
        float p2 = __shfl_xor_sync(~0u, v2, 1), p3 = __shfl_xor_sync(~0u, v3, 1);
        float p4 = __shfl_xor_sync(~0u, v4, 1), p5 = __shfl_xor_sync(~0u, v5, 1);
        float p6 = __shfl_xor_sync(~0u, v6, 1), p7 = __shfl_xor_sync(~0u, v7, 1);
        float a0 = b0 ? (v4 + p4) : (v0 + p0);   // row 4*b0 + 0
        float a1 = b0 ? (v5 + p5) : (v1 + p1);   // row 4*b0 + 1
        float a2 = b0 ? (v6 + p6) : (v2 + p2);   // row 4*b0 + 2
        float a3 = b0 ? (v7 + p7) : (v3 + p3);   // row 4*b0 + 3

        // Step 2 (xor 2): fold 4 -> 2.
        bool b1 = lane & 2;
        float q0 = __shfl_xor_sync(~0u, a0, 2), q1 = __shfl_xor_sync(~0u, a1, 2);
        float q2 = __shfl_xor_sync(~0u, a2, 2), q3 = __shfl_xor_sync(~0u, a3, 2);
        float c0 = b1 ? (a2 + q2) : (a0 + q0);   // row 4*b0 + 2*b1 + 0
        float c1 = b1 ? (a3 + q3) : (a1 + q1);   // row 4*b0 + 2*b1 + 1

        // Step 3 (xor 4): fold 2 -> 1.
        bool b2 = lane & 4;
        float s0 = __shfl_xor_sync(~0u, c0, 4), s1 = __shfl_xor_sync(~0u, c1, 4);
        float acc = b2 ? (c1 + s1) : (c0 + s0); // row rloc

        // Steps 4,5: reduce over remaining k-cosets (lane bits 3,4).
        acc += __shfl_xor_sync(~0u, acc, 8);
        acc += __shfl_xor_sync(~0u, acc, 16);

        if (lane < 8) {
            float y = acc + bias;
            out[(size_t)e * OUT_DIM + 8 * warp + rloc] = y > 0.f ? y : 0.f;
        }

        e  = e_next;
        xv = xv_next;
    }
}

// ---------------------------------------------------------------------------
extern "C" void kernel_launch(void* const* d_in, const int* in_sizes, int n_in,
                              void* d_out, int out_size) {
    const float* x     = (const float*)d_in[0];  // [E,128,1]
    const int*   idx   = (const int*)d_in[1];    // [E]
    const float* Wpool = (const float*)d_in[2];  // [P,64,128]
    const float* bpool = (const float*)d_in[3];  // [P,64,1]
    float* out = (float*)d_out;                  // [E,64,1]

    int E     = in_sizes[1];
    int npool = in_sizes[3] / OUT_DIM;

    void* counts_ptr = nullptr;
    cudaGetSymbolAddress(&counts_ptr, g_counts);
    cudaMemsetAsync(counts_ptr, 0, (size_t)npool * sizeof(int));

    int eb = (E + 255) / 256;
    hist_kernel<<<eb, 256>>>(idx, E);
    scan_kernel<<<1, 1024>>>(npool);
    scatter_kernel<<<eb, 256>>>(idx, E);
    compute_kernel<<<npool, 256>>>(x, Wpool, bpool, out);
}

// round 5
// speedup vs baseline: 1.4898x; 1.1164x over previous
#include <cuda_runtime.h>
#include <cuda_bf16.h>

#define OUT_DIM 64
#define IN_DIM 128
#define MAX_POOL 16384
#define MAX_EDGES 65536

__device__ int g_counts[MAX_POOL];
__device__ int g_offsets[MAX_POOL];
__device__ int g_cursor[MAX_POOL];
__device__ int g_sorted[MAX_EDGES];

// ---------------------------------------------------------------------------
__global__ void hist_kernel(const int* __restrict__ idx, int n) {
    int i = blockIdx.x * blockDim.x + threadIdx.x;
    if (i < n) atomicAdd(&g_counts[idx[i]], 1);
}

__global__ __launch_bounds__(1024) void scan_kernel(int npool) {
    int tid = threadIdx.x;
    int per = (npool + 1023) >> 10;
    int lo = min(tid * per, npool);
    int hi = min(lo + per, npool);
    int local[16];
    int sum = 0;
    for (int i = lo; i < hi; i++) { local[i - lo] = sum; sum += g_counts[i]; }
    int lane = tid & 31, wid = tid >> 5;
    int v = sum;
    #pragma unroll
    for (int o = 1; o < 32; o <<= 1) {
        int t = __shfl_up_sync(0xffffffffu, v, o);
        if (lane >= o) v += t;
    }
    __shared__ int ws[32];
    if (lane == 31) ws[wid] = v;
    __syncthreads();
    if (wid == 0) {
        int t = ws[lane];
        #pragma unroll
        for (int o = 1; o < 32; o <<= 1) {
            int u = __shfl_up_sync(0xffffffffu, t, o);
            if (lane >= o) t += u;
        }
        ws[lane] = t;
    }
    __syncthreads();
    int base = (v - sum) + (wid > 0 ? ws[wid - 1] : 0);
    for (int i = lo; i < hi; i++) {
        int off = base + local[i - lo];
        g_offsets[i] = off;
        g_cursor[i]  = off;
    }
}

__global__ void scatter_kernel(const int* __restrict__ idx, int n) {
    int i = blockIdx.x * blockDim.x + threadIdx.x;
    if (i < n) {
        int p = atomicAdd(&g_cursor[idx[i]], 1);
        g_sorted[p] = i;
    }
}

// ---------------------------------------------------------------------------
// Warp-autonomous compute, 2-edge software pipeline.
__device__ __forceinline__ void partials8(float v[8], const float4 wv[8],
                                          const float4& xv) {
    #pragma unroll
    for (int i = 0; i < 8; i++) v[i] = wv[i].x * xv.x;
    #pragma unroll
    for (int i = 0; i < 8; i++) v[i] = fmaf(wv[i].y, xv.y, v[i]);
    #pragma unroll
    for (int i = 0; i < 8; i++) v[i] = fmaf(wv[i].z, xv.z, v[i]);
    #pragma unroll
    for (int i = 0; i < 8; i++) v[i] = fmaf(wv[i].w, xv.w, v[i]);
}

// 5-stage butterfly: 8 row-partials x 32 lanes -> row (8*warp+rloc) in lanes 0..7
__device__ __forceinline__ float fold8(const float v[8], int lane) {
    bool b0 = lane & 1;
    float a0, a1, a2, a3;
    {
        float p0 = __shfl_xor_sync(~0u, v[0], 1), p1 = __shfl_xor_sync(~0u, v[1], 1);
        float p2 = __shfl_xor_sync(~0u, v[2], 1), p3 = __shfl_xor_sync(~0u, v[3], 1);
        float p4 = __shfl_xor_sync(~0u, v[4], 1), p5 = __shfl_xor_sync(~0u, v[5], 1);
        float p6 = __shfl_xor_sync(~0u, v[6], 1), p7 = __shfl_xor_sync(~0u, v[7], 1);
        a0 = b0 ? (v[4] + p4) : (v[0] + p0);
        a1 = b0 ? (v[5] + p5) : (v[1] + p1);
        a2 = b0 ? (v[6] + p6) : (v[2] + p2);
        a3 = b0 ? (v[7] + p7) : (v[3] + p3);
    }
    bool b1 = lane & 2;
    float c0, c1;
    {
        float q0 = __shfl_xor_sync(~0u, a0, 2), q1 = __shfl_xor_sync(~0u, a1, 2);
        float q2 = __shfl_xor_sync(~0u, a2, 2), q3 = __shfl_xor_sync(~0u, a3, 2);
        c0 = b1 ? (a2 + q2) : (a0 + q0);
        c1 = b1 ? (a3 + q3) : (a1 + q1);
    }
    bool b2 = lane & 4;
    float s0 = __shfl_xor_sync(~0u, c0, 4), s1 = __shfl_xor_sync(~0u, c1, 4);
    float acc = b2 ? (c1 + s1) : (c0 + s0);
    acc += __shfl_xor_sync(~0u, acc, 8);
    acc += __shfl_xor_sync(~0u, acc, 16);
    return acc;
}

__global__ __launch_bounds__(256) void compute_kernel(
    const float* __restrict__ x,      // [E, 128]
    const float* __restrict__ Wpool,  // [P, 64, 128]
    const float* __restrict__ bpool,  // [P, 64]
    float* __restrict__ out)          // [E, 64]
{
    int w    = blockIdx.x;
    int warp = threadIdx.x >> 5;
    int lane = threadIdx.x & 31;

    int cnt = g_counts[w];
    if (cnt == 0) return;
    int start = g_offsets[w];

    // W slice: 8 x LDG.128, each warp instruction covers 512B contiguous.
    const float4* Wg = reinterpret_cast<const float4*>(Wpool) + (size_t)w * 2048 + warp * 256;
    float4 wv[8];
    #pragma unroll
    for (int i = 0; i < 8; i++)
        wv[i] = Wg[i * 32 + lane];   // wv[i] = W[8*warp+i][4l..4l+4)

    int rloc = 4 * (lane & 1) + 2 * ((lane >> 1) & 1) + ((lane >> 2) & 1);
    float bias = bpool[(size_t)w * OUT_DIM + 8 * warp + rloc];
    int orow = 8 * warp + rloc;

    const float4* X = reinterpret_cast<const float4*>(x);

    // prime pipeline: edges 0,1
    int eA = g_sorted[start];
    float4 xA = X[(size_t)eA * 32 + lane];
    int eB = 0; float4 xB = make_float4(0.f, 0.f, 0.f, 0.f);
    if (cnt > 1) { eB = g_sorted[start + 1]; xB = X[(size_t)eB * 32 + lane]; }

    int t = 0;
    while (t + 2 <= cnt) {
        // prefetch next pair (depth-2)
        int eC = 0, eD = 0;
        float4 xC = make_float4(0.f, 0.f, 0.f, 0.f);
        float4 xD = make_float4(0.f, 0.f, 0.f, 0.f);
        if (t + 2 < cnt) { eC = g_sorted[start + t + 2]; xC = X[(size_t)eC * 32 + lane]; }
        if (t + 3 < cnt) { eD = g_sorted[start + t + 3]; xD = X[(size_t)eD * 32 + lane]; }

        // two independent partial sets (ILP 16 accumulators)
        float vA[8], vB[8];
        partials8(vA, wv, xA);
        partials8(vB, wv, xB);

        // two interleaved fold chains
        float accA = fold8(vA, lane);
        float accB = fold8(vB, lane);

        if (lane < 8) {
            float yA = accA + bias;
            float yB = accB + bias;
            out[(size_t)eA * OUT_DIM + orow] = yA > 0.f ? yA : 0.f;
            out[(size_t)eB * OUT_DIM + orow] = yB > 0.f ? yB : 0.f;
        }

        eA = eC; xA = xC;
        eB = eD; xB = xD;
        t += 2;
    }
    if (t < cnt) {          // odd tail
        float vA[8];
        partials8(vA, wv, xA);
        float accA = fold8(vA, lane);
        if (lane < 8) {
            float yA = accA + bias;
            out[(size_t)eA * OUT_DIM + orow] = yA > 0.f ? yA : 0.f;
        }
    }
}

// ---------------------------------------------------------------------------
extern "C" void kernel_launch(void* const* d_in, const int* in_sizes, int n_in,
                              void* d_out, int out_size) {
    const float* x     = (const float*)d_in[0];  // [E,128,1]
    const int*   idx   = (const int*)d_in[1];    // [E]
    const float* Wpool = (const float*)d_in[2];  // [P,64,128]
    const float* bpool = (const float*)d_in[3];  // [P,64,1]
    float* out = (float*)d_out;                  // [E,64,1]

    int E     = in_sizes[1];
    int npool = in_sizes[3] / OUT_DIM;

    void* counts_ptr = nullptr;
    cudaGetSymbolAddress(&counts_ptr, g_counts);
    cudaMemsetAsync(counts_ptr, 0, (size_t)npool * sizeof(int));

    int eb = (E + 255) / 256;
    hist_kernel<<<eb, 256>>>(idx, E);
    scan_kernel<<<1, 1024>>>(npool);
    scatter_kernel<<<eb, 256>>>(idx, E);
    compute_kernel<<<npool, 256>>>(x, Wpool, bpool, out);
}